// round 2
// baseline (speedup 1.0000x reference)
#include <cuda_runtime.h>
#include <math.h>

#define NB 32
#define NC 64
#define NL 2048
#define NBINS 1025
#define S0 341
#define S1 341
#define S2 343
#define PAD 344     // row stride for band / Y storage
#define SPAD 345    // shared-memory row stride (bank-conflict padding)
#define NROWS 2048  // NB * NC

// Scratch (device globals; allocation-free per harness rules)
__device__ float g_bands[3][NROWS][PAD];
__device__ float g_Y[3][NROWS][PAD];
__device__ float g_dist[3][NB][NC][NC];

// ---------------------------------------------------------------------------
// Kernel 1: radix-2 DIT FFT (N=2048, complex-from-real) + |.| into band slabs
// one block per (b,c) signal, 512 threads
// ---------------------------------------------------------------------------
__global__ __launch_bounds__(512) void fft_mag_kernel(const float* __restrict__ X) {
    __shared__ float sre[NL];
    __shared__ float sim[NL];
    __shared__ float wre[1024];
    __shared__ float wim[1024];

    const int row = blockIdx.x;
    const int t = threadIdx.x;
    const float* x = X + (size_t)row * NL;

    // twiddle LUT: W[j] = exp(-i*pi*j/1024)
    for (int i = t; i < 1024; i += 512) {
        float s, c;
        sincospif((float)i * (1.0f / 1024.0f), &s, &c);
        wre[i] = c;
        wim[i] = -s;
    }
    // bit-reversed load (11-bit reversal)
    for (int i = t; i < NL; i += 512) {
        int r = __brev((unsigned)i) >> 21;
        sre[r] = x[i];
        sim[r] = 0.0f;
    }
    __syncthreads();

    #pragma unroll
    for (int s = 1; s <= 11; s++) {
        const int half = 1 << (s - 1);
        const int tw_shift = 11 - s; // LUT index stride = 1024/half
        for (int u = t; u < 1024; u += 512) {
            const int j = u & (half - 1);
            const int base = (u >> (s - 1)) << s;
            const int p0 = base + j;
            const int p1 = p0 + half;
            const int wi = j << tw_shift;
            const float wr = wre[wi];
            const float wm = wim[wi];
            const float ar = sre[p0], ai = sim[p0];
            const float br = sre[p1], bi = sim[p1];
            const float vr = br * wr - bi * wm;
            const float vi = br * wm + bi * wr;
            sre[p0] = ar + vr;
            sim[p0] = ai + vi;
            sre[p1] = ar - vr;
            sim[p1] = ai - vi;
        }
        __syncthreads();
    }

    for (int i = t; i < NBINS; i += 512) {
        const float re = sre[i], im = sim[i];
        const float mag = sqrtf(re * re + im * im);
        if (i < S0)            g_bands[0][row][i] = mag;
        else if (i < S0 + S1)  g_bands[1][row][i - S0] = mag;
        else                   g_bands[2][row][i - S0 - S1] = mag;
    }
}

// ---------------------------------------------------------------------------
// Kernel 2: Y[k][r][d] = sum_s band[k][r][s] * A_k[d][s]
// tiled 64x64, 256 threads, 4x4 per thread, K-tile 16
// grid: (6, 32, 3)
// ---------------------------------------------------------------------------
__global__ __launch_bounds__(256) void gemm_y_kernel(const float* __restrict__ A0,
                                                     const float* __restrict__ A1,
                                                     const float* __restrict__ A2) {
    __shared__ float Xs[64][17];
    __shared__ float Aa[64][17];

    const int k = blockIdx.z;
    const int sk = (k == 2) ? S2 : S0;
    const float* A = (k == 0) ? A0 : ((k == 1) ? A1 : A2);
    const float* band = &g_bands[k][0][0];

    const int d0 = blockIdx.x * 64;
    const int r0 = blockIdx.y * 64;
    const int t = threadIdx.x;
    const int tx = t & 15;      // d groups
    const int ty = t >> 4;      // r groups

    float acc[4][4];
    #pragma unroll
    for (int i = 0; i < 4; i++)
        #pragma unroll
        for (int j = 0; j < 4; j++) acc[i][j] = 0.0f;

    for (int kt = 0; kt < sk; kt += 16) {
        // cooperative loads: 1024 elements per tile, 4 per thread
        #pragma unroll
        for (int n = 0; n < 4; n++) {
            const int e = t + n * 256;
            const int rr = e >> 4;
            const int cc = e & 15;
            const int s = kt + cc;
            Xs[rr][cc] = (s < sk) ? band[(size_t)(r0 + rr) * PAD + s] : 0.0f;
            const int d = d0 + rr;
            Aa[rr][cc] = (s < sk && d < sk) ? A[(size_t)d * sk + s] : 0.0f;
        }
        __syncthreads();
        #pragma unroll
        for (int kk = 0; kk < 16; kk++) {
            float a[4], bb[4];
            #pragma unroll
            for (int i = 0; i < 4; i++) a[i] = Xs[ty * 4 + i][kk];
            #pragma unroll
            for (int j = 0; j < 4; j++) bb[j] = Aa[tx * 4 + j][kk];
            #pragma unroll
            for (int i = 0; i < 4; i++)
                #pragma unroll
                for (int j = 0; j < 4; j++) acc[i][j] += a[i] * bb[j];
        }
        __syncthreads();
    }

    #pragma unroll
    for (int i = 0; i < 4; i++) {
        const int r = r0 + ty * 4 + i;
        #pragma unroll
        for (int j = 0; j < 4; j++) {
            const int d = d0 + tx * 4 + j;
            if (d < sk) g_Y[k][r][d] = acc[i][j];
        }
    }
}

// ---------------------------------------------------------------------------
// Kernel 3: per (batch b, band k): G = Y Y^T, q = diag, dist = relu(q_i+q_j-2G)
// block = 256 threads; whole 64 x sk Y-slab staged in dynamic smem (stride 345)
// grid: (32, 3)
// ---------------------------------------------------------------------------
__global__ __launch_bounds__(256) void gram_dist_kernel() {
    extern __shared__ float sY[];        // 64 * SPAD floats
    __shared__ float q[64];

    const int b = blockIdx.x;
    const int k = blockIdx.y;
    const int sk = (k == 2) ? S2 : S0;
    const int t = threadIdx.x;

    const float* src = &g_Y[k][b * 64][0];   // 64*PAD contiguous floats
    for (int idx = t; idx < 64 * PAD; idx += 256) {
        const int row = idx / PAD;
        sY[idx + row] = src[idx];            // re-stride PAD -> SPAD
    }
    __syncthreads();

    if (t < 64) {
        float a = 0.0f;
        const float* r = &sY[t * SPAD];
        for (int d = 0; d < sk; d++) a += r[d] * r[d];
        q[t] = a;
    }
    __syncthreads();

    const int ti = (t >> 4) * 4;
    const int tj = (t & 15) * 4;
    float acc[4][4];
    #pragma unroll
    for (int i = 0; i < 4; i++)
        #pragma unroll
        for (int j = 0; j < 4; j++) acc[i][j] = 0.0f;

    for (int d = 0; d < sk; d++) {
        float a[4], bb[4];
        #pragma unroll
        for (int i = 0; i < 4; i++) a[i] = sY[(ti + i) * SPAD + d];
        #pragma unroll
        for (int j = 0; j < 4; j++) bb[j] = sY[(tj + j) * SPAD + d];
        #pragma unroll
        for (int i = 0; i < 4; i++)
            #pragma unroll
            for (int j = 0; j < 4; j++) acc[i][j] += a[i] * bb[j];
    }

    #pragma unroll
    for (int i = 0; i < 4; i++) {
        #pragma unroll
        for (int j = 0; j < 4; j++) {
            const int ii = ti + i, jj = tj + j;
            float dist = q[ii] + q[jj] - 2.0f * acc[i][j];
            dist = fmaxf(dist, 0.0f);
            g_dist[k][b][ii][jj] = dist;
        }
    }
}

// ---------------------------------------------------------------------------
// Kernel 4: fuse bands, row-max of 1/dist, p, logits, gumbel argmax -> binary
// one block (64 threads) per (b, i) row; grid = 2048
// ---------------------------------------------------------------------------
__global__ __launch_bounds__(64) void mask_kernel(const float* __restrict__ fw,
                                                  const float* __restrict__ gum,
                                                  float* __restrict__ out) {
    const int bi = blockIdx.x;
    const int b = bi >> 6;
    const int i = bi & 63;
    const int j = threadIdx.x;

    // softmax of fusion weights (stable, f32 like jax.nn.softmax)
    const float f0 = fw[0], f1 = fw[1], f2 = fw[2];
    const float m = fmaxf(f0, fmaxf(f1, f2));
    const float e0 = expf(f0 - m), e1 = expf(f1 - m), e2 = expf(f2 - m);
    const float inv = 1.0f / (e0 + e1 + e2);
    const float w0 = e0 * inv, w1 = e1 * inv, w2 = e2 * inv;

    const float dsum = g_dist[0][b][i][j] * w0
                     + g_dist[1][b][i][j] * w1
                     + g_dist[2][b][i][j] * w2;

    const float e = 1.0f / (dsum + 1e-10f);
    const float emask = (j == i) ? 0.0f : e;

    // max-reduce over 64 threads (2 warps)
    __shared__ float red[2];
    float v = emask;
    #pragma unroll
    for (int o = 16; o; o >>= 1) v = fmaxf(v, __shfl_xor_sync(0xffffffffu, v, o));
    if ((j & 31) == 0) red[j >> 5] = v;
    __syncthreads();
    const float emax = fmaxf(red[0], red[1]);

    float p = emask / emax;
    p = (j == i) ? 0.99f : p * 0.99f;

    const float l0 = logf(p / (1.0f - p));
    const float l1 = logf((1.0f - p) / p);

    const size_t gidx = ((size_t)(b * 4096 + i * 64 + j)) * 2;
    const float y0 = l0 + gum[gidx + 0];
    const float y1 = l1 + gum[gidx + 1];

    out[b * 4096 + i * 64 + j] = (y0 >= y1) ? 1.0f : 0.0f;
}

// ---------------------------------------------------------------------------
extern "C" void kernel_launch(void* const* d_in, const int* in_sizes, int n_in,
                              void* d_out, int out_size) {
    const float* X   = (const float*)d_in[0];
    const float* A0  = (const float*)d_in[1];
    const float* A1  = (const float*)d_in[2];
    const float* A2  = (const float*)d_in[3];
    const float* fw  = (const float*)d_in[4];
    const float* gum = (const float*)d_in[5];
    float* out = (float*)d_out;

    fft_mag_kernel<<<NROWS, 512>>>(X);

    dim3 g2(6, 32, 3);
    gemm_y_kernel<<<g2, 256>>>(A0, A1, A2);

    const int smem3 = 64 * SPAD * sizeof(float);
    cudaFuncSetAttribute(gram_dist_kernel,
                         cudaFuncAttributeMaxDynamicSharedMemorySize, smem3);
    gram_dist_kernel<<<dim3(NB, 3), 256, smem3>>>();

    mask_kernel<<<NROWS, 64>>>(fw, gum, out);
}

// round 3
// speedup vs baseline: 2.8966x; 2.8966x over previous
#include <cuda_runtime.h>
#include <math.h>

#define NB 32
#define NC 64
#define NL 2048
#define S0 341
#define S1 341
#define S2 343
#define SKP 352      // padded stride for bands / Y / Apad (K dim)
#define DP  384      // padded d dimension
#define SPAD 353     // gram smem row stride
#define NROWS 2048   // NB * NC

// Scratch (device globals; allocation-free per harness rules)
__device__ float g_bands[3][NROWS][SKP];
__device__ float g_Y[3][NROWS][SKP];
__device__ float g_Apad[3][DP][SKP];
__device__ float g_dist[3][NB][NC][NC];

// ---------------------------------------------------------------------------
// f32x2 helpers (Blackwell packed fp32: FFMA2)
// ---------------------------------------------------------------------------
__device__ __forceinline__ unsigned long long pk2(float lo, float hi) {
    unsigned long long r;
    asm("mov.b64 %0, {%1, %2};" : "=l"(r) : "f"(lo), "f"(hi));
    return r;
}
__device__ __forceinline__ void fma2(unsigned long long& d,
                                     unsigned long long a, unsigned long long b) {
    asm("fma.rn.f32x2 %0, %1, %2, %0;" : "+l"(d) : "l"(a), "l"(b));
}
__device__ __forceinline__ float2 upk2(unsigned long long v) {
    float lo, hi;
    asm("mov.b64 {%0, %1}, %2;" : "=f"(lo), "=f"(hi) : "l"(v));
    return make_float2(lo, hi);
}

// ---------------------------------------------------------------------------
// Kernel 0: pad A matrices into g_Apad (zero-filled to 384 x 352)
// grid (DP, 3), 256 threads
// ---------------------------------------------------------------------------
__global__ __launch_bounds__(256) void prep_kernel(const float* __restrict__ A0,
                                                   const float* __restrict__ A1,
                                                   const float* __restrict__ A2) {
    const int d = blockIdx.x;
    const int k = blockIdx.y;
    const int sk = (k == 2) ? S2 : S0;
    const float* A = (k == 0) ? A0 : ((k == 1) ? A1 : A2);
    float* dst = &g_Apad[k][d][0];
    for (int s = threadIdx.x; s < SKP; s += 256)
        dst[s] = (d < sk && s < sk) ? A[(size_t)d * sk + s] : 0.0f;
}

// ---------------------------------------------------------------------------
// Kernel 1: rfft magnitude via real-packed 1024-pt radix-4 FFT
// one block per (b,c) signal, 256 threads, 16KB smem
// ---------------------------------------------------------------------------
__device__ __forceinline__ unsigned drev10(unsigned n) {
    unsigned r = __brev(n) >> 22;                       // 10-bit bit reversal
    return ((r & 0x155u) << 1) | ((r >> 1) & 0x155u);   // swap adjacent bits -> base-4 digit reversal
}

__global__ __launch_bounds__(256) void fft_kernel(const float* __restrict__ X) {
    __shared__ float sre[1024], sim[1024], wre[1024], wim[1024];
    const int row = blockIdx.x;
    const int t = threadIdx.x;
    const float2* x2 = (const float2*)(X + (size_t)row * NL);

    #pragma unroll
    for (int m = 0; m < 4; m++) {
        const int i = t + m * 256;
        float sn, cs;
        sincospif((float)i * (1.0f / 512.0f), &sn, &cs);  // e^{-2*pi*i*i/1024}
        wre[i] = cs;
        wim[i] = -sn;
        const float2 v = x2[i];       // z[i] = x[2i] + i*x[2i+1]
        const unsigned dr = drev10((unsigned)i);
        sre[dr] = v.x;
        sim[dr] = v.y;
    }
    __syncthreads();

    // stage 1 (m=1): contiguous quads, twiddle = 1, float4 access
    {
        float4 xr = *(float4*)&sre[4 * t];
        float4 xi = *(float4*)&sim[4 * t];
        const float s02r = xr.x + xr.z, s02i = xi.x + xi.z;
        const float d02r = xr.x - xr.z, d02i = xi.x - xi.z;
        const float s13r = xr.y + xr.w, s13i = xi.y + xi.w;
        const float d13r = xr.y - xr.w, d13i = xi.y - xi.w;
        float4 yr, yi;
        yr.x = s02r + s13r;  yi.x = s02i + s13i;
        yr.y = d02r + d13i;  yi.y = d02i - d13r;
        yr.z = s02r - s13r;  yi.z = s02i - s13i;
        yr.w = d02r - d13i;  yi.w = d02i + d13r;
        *(float4*)&sre[4 * t] = yr;
        *(float4*)&sim[4 * t] = yi;
    }
    __syncthreads();

    // stages 2..5
    #pragma unroll
    for (int s = 2; s <= 5; s++) {
        const int mm = 1 << (2 * (s - 1));
        const int j = t & (mm - 1);
        const int base = ((t >> (2 * (s - 1))) << (2 * s)) + j;
        const int r1 = j << (10 - 2 * s);

        const float x0r = sre[base],          x0i = sim[base];
        const float x1r = sre[base + mm],     x1i = sim[base + mm];
        const float x2r = sre[base + 2 * mm], x2i = sim[base + 2 * mm];
        const float x3r = sre[base + 3 * mm], x3i = sim[base + 3 * mm];
        const float w1r = wre[r1],     w1i = wim[r1];
        const float w2r = wre[2 * r1], w2i = wim[2 * r1];
        const float w3r = wre[3 * r1], w3i = wim[3 * r1];

        const float u1r = x1r * w1r - x1i * w1i, u1i = x1r * w1i + x1i * w1r;
        const float u2r = x2r * w2r - x2i * w2i, u2i = x2r * w2i + x2i * w2r;
        const float u3r = x3r * w3r - x3i * w3i, u3i = x3r * w3i + x3i * w3r;

        const float s02r = x0r + u2r, s02i = x0i + u2i;
        const float d02r = x0r - u2r, d02i = x0i - u2i;
        const float s13r = u1r + u3r, s13i = u1i + u3i;
        const float d13r = u1r - u3r, d13i = u1i - u3i;

        sre[base]          = s02r + s13r;  sim[base]          = s02i + s13i;
        sre[base + mm]     = d02r + d13i;  sim[base + mm]     = d02i - d13r;
        sre[base + 2 * mm] = s02r - s13r;  sim[base + 2 * mm] = s02i - s13i;
        sre[base + 3 * mm] = d02r - d13i;  sim[base + 3 * mm] = d02i + d13r;
        __syncthreads();
    }

    // untangle real-packed spectrum + magnitude -> zero-padded band slabs
    for (int pos = t; pos < 3 * SKP; pos += 256) {
        int band, off, k, sk;
        if (pos < SKP)            { band = 0; off = pos;           k = off;       sk = S0; }
        else if (pos < 2 * SKP)   { band = 1; off = pos - SKP;     k = S0 + off;  sk = S1; }
        else                      { band = 2; off = pos - 2 * SKP; k = 682 + off; sk = S2; }
        float mag = 0.0f;
        if (off < sk) {
            const int ka = k & 1023;
            const int kb = (1024 - k) & 1023;
            const float z1r = sre[ka], z1i = sim[ka];
            const float z2r = sre[kb], z2i = sim[kb];
            const float zer = z1r + z2r, zei = z1i - z2i;        // 2*Ze
            const float zor = z1i + z2i, zoi = z2r - z1r;        // 2*Zo
            float sn, cs;
            sincospif((float)k * (1.0f / 1024.0f), &sn, &cs);    // w = (cs, -sn)
            const float xr = zer + cs * zor + sn * zoi;
            const float xi = zei + cs * zoi - sn * zor;
            mag = 0.5f * sqrtf(xr * xr + xi * xi);
        }
        (&g_bands[0][0][0])[((size_t)band * NROWS + row) * SKP + off] = mag;
    }
}

// ---------------------------------------------------------------------------
// Kernel 2: Y[k][r][d] = sum_s band[k][r][s] * Apad[k][d][s]
// 128x128 tiles, 256 threads, 8x8 per thread, f32x2 FMA, double-buffered smem
// grid (3, 16, 3)
// ---------------------------------------------------------------------------
__global__ __launch_bounds__(256) void gemm_kernel() {
    __shared__ float Xs[2][16][128];
    __shared__ float As[2][16][128];

    const int k = blockIdx.z;
    const int d0 = blockIdx.x * 128;
    const int r0 = blockIdx.y * 128;
    const int t = threadIdx.x;
    const int tx = t & 15;
    const int ty = t >> 4;
    const float* band = &g_bands[k][0][0];
    const float* Ap = &g_Apad[k][0][0];

    const int lr = t & 127;          // row within tile for loading
    const int lh = (t >> 7) * 8;     // s-offset 0 or 8

    unsigned long long acc[8][4];
    #pragma unroll
    for (int i = 0; i < 8; i++)
        #pragma unroll
        for (int j = 0; j < 4; j++) acc[i][j] = 0ull;

    float4 bx0, bx1, ba0, ba1;

#define LDG_TILE(kt)                                                            \
    do {                                                                        \
        const float* xp = &band[(size_t)(r0 + lr) * SKP + (kt) + lh];           \
        const float* ap = &Ap[(size_t)(d0 + lr) * SKP + (kt) + lh];             \
        bx0 = *(const float4*)xp;  bx1 = *(const float4*)(xp + 4);              \
        ba0 = *(const float4*)ap;  ba1 = *(const float4*)(ap + 4);              \
    } while (0)

#define STS_TILE(buf)                                                           \
    do {                                                                        \
        Xs[buf][lh + 0][lr] = bx0.x;  Xs[buf][lh + 1][lr] = bx0.y;              \
        Xs[buf][lh + 2][lr] = bx0.z;  Xs[buf][lh + 3][lr] = bx0.w;              \
        Xs[buf][lh + 4][lr] = bx1.x;  Xs[buf][lh + 5][lr] = bx1.y;              \
        Xs[buf][lh + 6][lr] = bx1.z;  Xs[buf][lh + 7][lr] = bx1.w;              \
        As[buf][lh + 0][lr] = ba0.x;  As[buf][lh + 1][lr] = ba0.y;              \
        As[buf][lh + 2][lr] = ba0.z;  As[buf][lh + 3][lr] = ba0.w;              \
        As[buf][lh + 4][lr] = ba1.x;  As[buf][lh + 5][lr] = ba1.y;              \
        As[buf][lh + 6][lr] = ba1.z;  As[buf][lh + 7][lr] = ba1.w;              \
    } while (0)

    LDG_TILE(0);
    STS_TILE(0);
    __syncthreads();

    const int NT = SKP / 16;  // 22
    for (int kt = 0; kt < NT; kt++) {
        const int buf = kt & 1;
        if (kt + 1 < NT) LDG_TILE((kt + 1) * 16);

        #pragma unroll
        for (int kk = 0; kk < 16; kk++) {
            const float4 a0 = *(const float4*)&Xs[buf][kk][ty * 8];
            const float4 a1 = *(const float4*)&Xs[buf][kk][ty * 8 + 4];
            const float4 b0 = *(const float4*)&As[buf][kk][tx * 8];
            const float4 b1 = *(const float4*)&As[buf][kk][tx * 8 + 4];
            const unsigned long long bp0 = pk2(b0.x, b0.y);
            const unsigned long long bp1 = pk2(b0.z, b0.w);
            const unsigned long long bp2 = pk2(b1.x, b1.y);
            const unsigned long long bp3 = pk2(b1.z, b1.w);
            const float av[8] = {a0.x, a0.y, a0.z, a0.w, a1.x, a1.y, a1.z, a1.w};
            #pragma unroll
            for (int i = 0; i < 8; i++) {
                const unsigned long long ad = pk2(av[i], av[i]);
                fma2(acc[i][0], ad, bp0);
                fma2(acc[i][1], ad, bp1);
                fma2(acc[i][2], ad, bp2);
                fma2(acc[i][3], ad, bp3);
            }
        }
        if (kt + 1 < NT) STS_TILE(buf ^ 1);
        __syncthreads();
    }

    #pragma unroll
    for (int i = 0; i < 8; i++) {
        const int r = r0 + ty * 8 + i;
        float* yrow = &g_Y[k][r][0];
        #pragma unroll
        for (int j2 = 0; j2 < 4; j2++) {
            const int d = d0 + tx * 8 + j2 * 2;
            if (d < SKP) *(float2*)&yrow[d] = upk2(acc[i][j2]);
        }
    }
#undef LDG_TILE
#undef STS_TILE
}

// ---------------------------------------------------------------------------
// Kernel 3: per (batch b, band k): dist = relu(q_i + q_j - 2 * Yi.Yj)
// fixed 352-length inner loop (padded zeros are harmless)
// grid (32, 3), 256 threads, dynamic smem 64*353*4
// ---------------------------------------------------------------------------
__global__ __launch_bounds__(256) void gram_dist_kernel() {
    extern __shared__ float sY[];        // 64 * SPAD floats
    __shared__ float q[64];

    const int b = blockIdx.x;
    const int k = blockIdx.y;
    const int t = threadIdx.x;

    const float* src = &g_Y[k][b * 64][0];   // 64*SKP contiguous floats
    for (int idx = t; idx < 64 * SKP; idx += 256) {
        const int row = idx / SKP;
        sY[idx + row] = src[idx];            // re-stride SKP -> SPAD
    }
    __syncthreads();

    if (t < 64) {
        float a = 0.0f;
        const float* r = &sY[t * SPAD];
        #pragma unroll 4
        for (int d = 0; d < SKP; d++) a += r[d] * r[d];
        q[t] = a;
    }
    __syncthreads();

    const int ti = (t >> 4) * 4;
    const int tj = (t & 15) * 4;
    float acc[4][4];
    #pragma unroll
    for (int i = 0; i < 4; i++)
        #pragma unroll
        for (int j = 0; j < 4; j++) acc[i][j] = 0.0f;

    #pragma unroll 2
    for (int d = 0; d < SKP; d++) {
        float a[4], bb[4];
        #pragma unroll
        for (int i = 0; i < 4; i++) a[i] = sY[(ti + i) * SPAD + d];
        #pragma unroll
        for (int j = 0; j < 4; j++) bb[j] = sY[(tj + j) * SPAD + d];
        #pragma unroll
        for (int i = 0; i < 4; i++)
            #pragma unroll
            for (int j = 0; j < 4; j++) acc[i][j] += a[i] * bb[j];
    }

    #pragma unroll
    for (int i = 0; i < 4; i++) {
        #pragma unroll
        for (int j = 0; j < 4; j++) {
            const int ii = ti + i, jj = tj + j;
            float dist = q[ii] + q[jj] - 2.0f * acc[i][j];
            g_dist[k][b][ii][jj] = fmaxf(dist, 0.0f);
        }
    }
}

// ---------------------------------------------------------------------------
// Kernel 4: fuse bands, row-max of 1/dist, p, logits, gumbel argmax -> binary
// 256 threads = 4 rows per block; grid = 512
// ---------------------------------------------------------------------------
__global__ __launch_bounds__(256) void mask_kernel(const float* __restrict__ fw,
                                                   const float* __restrict__ gum,
                                                   float* __restrict__ out) {
    const int t = threadIdx.x;
    const int g = t >> 6;               // row slice within block
    const int j = t & 63;
    const int bi = blockIdx.x * 4 + g;
    const int b = bi >> 6;
    const int i = bi & 63;

    const float f0 = fw[0], f1 = fw[1], f2 = fw[2];
    const float m = fmaxf(f0, fmaxf(f1, f2));
    const float e0 = expf(f0 - m), e1 = expf(f1 - m), e2 = expf(f2 - m);
    const float inv = 1.0f / (e0 + e1 + e2);
    const float w0 = e0 * inv, w1 = e1 * inv, w2 = e2 * inv;

    const float dsum = g_dist[0][b][i][j] * w0
                     + g_dist[1][b][i][j] * w1
                     + g_dist[2][b][i][j] * w2;

    const float e = 1.0f / (dsum + 1e-10f);
    const float emask = (j == i) ? 0.0f : e;

    __shared__ float red[8];
    float v = emask;
    #pragma unroll
    for (int o = 16; o; o >>= 1) v = fmaxf(v, __shfl_xor_sync(0xffffffffu, v, o));
    if ((t & 31) == 0) red[t >> 5] = v;
    __syncthreads();
    const float emax = fmaxf(red[2 * g], red[2 * g + 1]);

    float p = emask / emax;
    p = (j == i) ? 0.99f : p * 0.99f;

    const float l0 = logf(p / (1.0f - p));
    const float l1 = logf((1.0f - p) / p);

    const size_t gidx = ((size_t)(b * 4096 + i * 64 + j)) * 2;
    const float y0 = l0 + gum[gidx + 0];
    const float y1 = l1 + gum[gidx + 1];

    out[b * 4096 + i * 64 + j] = (y0 >= y1) ? 1.0f : 0.0f;
}

// ---------------------------------------------------------------------------
extern "C" void kernel_launch(void* const* d_in, const int* in_sizes, int n_in,
                              void* d_out, int out_size) {
    const float* X   = (const float*)d_in[0];
    const float* A0  = (const float*)d_in[1];
    const float* A1  = (const float*)d_in[2];
    const float* A2  = (const float*)d_in[3];
    const float* fw  = (const float*)d_in[4];
    const float* gum = (const float*)d_in[5];
    float* out = (float*)d_out;

    prep_kernel<<<dim3(DP, 3), 256>>>(A0, A1, A2);
    fft_kernel<<<NROWS, 256>>>(X);
    gemm_kernel<<<dim3(3, 16, 3), 256>>>();

    const int smem3 = 64 * SPAD * sizeof(float);
    cudaFuncSetAttribute(gram_dist_kernel,
                         cudaFuncAttributeMaxDynamicSharedMemorySize, smem3);
    gram_dist_kernel<<<dim3(NB, 3), 256, smem3>>>();

    mask_kernel<<<512, 256>>>(fw, gum, out);
}

// round 4
// speedup vs baseline: 3.2286x; 1.1146x over previous
#include <cuda_runtime.h>
#include <math.h>

#define NB 32
#define NC 64
#define NL 2048
#define S0 341
#define S1 341
#define S2 343
#define SKP 352      // padded stride for bands / Y / Apad (K dim)
#define DP  384      // padded d dimension
#define TSP 68       // gram transposed-smem row stride (64 + 4)
#define NROWS 2048   // NB * NC

// Scratch (device globals; allocation-free per harness rules)
__device__ float g_bands[3][NROWS][SKP];
__device__ float g_Y[3][NROWS][SKP];
__device__ float g_Apad[3][DP][SKP];
__device__ float g_dist[3][NB][NC][NC];

// ---------------------------------------------------------------------------
// f32x2 helpers (Blackwell packed fp32: FFMA2)
// ---------------------------------------------------------------------------
__device__ __forceinline__ unsigned long long pk2(float lo, float hi) {
    unsigned long long r;
    asm("mov.b64 %0, {%1, %2};" : "=l"(r) : "f"(lo), "f"(hi));
    return r;
}
__device__ __forceinline__ void fma2(unsigned long long& d,
                                     unsigned long long a, unsigned long long b) {
    asm("fma.rn.f32x2 %0, %1, %2, %0;" : "+l"(d) : "l"(a), "l"(b));
}
__device__ __forceinline__ float2 upk2(unsigned long long v) {
    float lo, hi;
    asm("mov.b64 {%0, %1}, %2;" : "=f"(lo), "=f"(hi) : "l"(v));
    return make_float2(lo, hi);
}

// ---------------------------------------------------------------------------
// Kernel 0: pad A matrices into g_Apad (zero-filled to 384 x 352)
// ---------------------------------------------------------------------------
__global__ __launch_bounds__(256) void prep_kernel(const float* __restrict__ A0,
                                                   const float* __restrict__ A1,
                                                   const float* __restrict__ A2) {
    const int d = blockIdx.x;
    const int k = blockIdx.y;
    const int sk = (k == 2) ? S2 : S0;
    const float* A = (k == 0) ? A0 : ((k == 1) ? A1 : A2);
    float* dst = &g_Apad[k][d][0];
    for (int s = threadIdx.x; s < SKP; s += 256)
        dst[s] = (d < sk && s < sk) ? A[(size_t)d * sk + s] : 0.0f;
}

// ---------------------------------------------------------------------------
// Kernel 1: rfft magnitude via real-packed 1024-pt radix-4 FFT
// ---------------------------------------------------------------------------
__device__ __forceinline__ unsigned drev10(unsigned n) {
    unsigned r = __brev(n) >> 22;                       // 10-bit bit reversal
    return ((r & 0x155u) << 1) | ((r >> 1) & 0x155u);   // -> base-4 digit reversal
}

__global__ __launch_bounds__(256) void fft_kernel(const float* __restrict__ X) {
    __shared__ float sre[1024], sim[1024], wre[1024], wim[1024];
    const int row = blockIdx.x;
    const int t = threadIdx.x;
    const float2* x2 = (const float2*)(X + (size_t)row * NL);

    #pragma unroll
    for (int m = 0; m < 4; m++) {
        const int i = t + m * 256;
        float sn, cs;
        sincospif((float)i * (1.0f / 512.0f), &sn, &cs);  // e^{-2*pi*i*i/1024}
        wre[i] = cs;
        wim[i] = -sn;
        const float2 v = x2[i];       // z[i] = x[2i] + i*x[2i+1]
        const unsigned dr = drev10((unsigned)i);
        sre[dr] = v.x;
        sim[dr] = v.y;
    }
    __syncthreads();

    // stage 1 (m=1): contiguous quads, twiddle = 1, float4 access
    {
        float4 xr = *(float4*)&sre[4 * t];
        float4 xi = *(float4*)&sim[4 * t];
        const float s02r = xr.x + xr.z, s02i = xi.x + xi.z;
        const float d02r = xr.x - xr.z, d02i = xi.x - xi.z;
        const float s13r = xr.y + xr.w, s13i = xi.y + xi.w;
        const float d13r = xr.y - xr.w, d13i = xi.y - xi.w;
        float4 yr, yi;
        yr.x = s02r + s13r;  yi.x = s02i + s13i;
        yr.y = d02r + d13i;  yi.y = d02i - d13r;
        yr.z = s02r - s13r;  yi.z = s02i - s13i;
        yr.w = d02r - d13i;  yi.w = d02i + d13r;
        *(float4*)&sre[4 * t] = yr;
        *(float4*)&sim[4 * t] = yi;
    }
    __syncthreads();

    // stages 2..5
    #pragma unroll
    for (int s = 2; s <= 5; s++) {
        const int mm = 1 << (2 * (s - 1));
        const int j = t & (mm - 1);
        const int base = ((t >> (2 * (s - 1))) << (2 * s)) + j;
        const int r1 = j << (10 - 2 * s);

        const float x0r = sre[base],          x0i = sim[base];
        const float x1r = sre[base + mm],     x1i = sim[base + mm];
        const float x2r = sre[base + 2 * mm], x2i = sim[base + 2 * mm];
        const float x3r = sre[base + 3 * mm], x3i = sim[base + 3 * mm];
        const float w1r = wre[r1],     w1i = wim[r1];
        const float w2r = wre[2 * r1], w2i = wim[2 * r1];
        const float w3r = wre[3 * r1], w3i = wim[3 * r1];

        const float u1r = x1r * w1r - x1i * w1i, u1i = x1r * w1i + x1i * w1r;
        const float u2r = x2r * w2r - x2i * w2i, u2i = x2r * w2i + x2i * w2r;
        const float u3r = x3r * w3r - x3i * w3i, u3i = x3r * w3i + x3i * w3r;

        const float s02r = x0r + u2r, s02i = x0i + u2i;
        const float d02r = x0r - u2r, d02i = x0i - u2i;
        const float s13r = u1r + u3r, s13i = u1i + u3i;
        const float d13r = u1r - u3r, d13i = u1i - u3i;

        sre[base]          = s02r + s13r;  sim[base]          = s02i + s13i;
        sre[base + mm]     = d02r + d13i;  sim[base + mm]     = d02i - d13r;
        sre[base + 2 * mm] = s02r - s13r;  sim[base + 2 * mm] = s02i - s13i;
        sre[base + 3 * mm] = d02r - d13i;  sim[base + 3 * mm] = d02i + d13r;
        __syncthreads();
    }

    // untangle real-packed spectrum + magnitude -> zero-padded band slabs
    for (int pos = t; pos < 3 * SKP; pos += 256) {
        int band, off, k, sk;
        if (pos < SKP)            { band = 0; off = pos;           k = off;       sk = S0; }
        else if (pos < 2 * SKP)   { band = 1; off = pos - SKP;     k = S0 + off;  sk = S1; }
        else                      { band = 2; off = pos - 2 * SKP; k = 682 + off; sk = S2; }
        float mag = 0.0f;
        if (off < sk) {
            const int ka = k & 1023;
            const int kb = (1024 - k) & 1023;
            const float z1r = sre[ka], z1i = sim[ka];
            const float z2r = sre[kb], z2i = sim[kb];
            const float zer = z1r + z2r, zei = z1i - z2i;        // 2*Ze
            const float zor = z1i + z2i, zoi = z2r - z1r;        // 2*Zo
            float sn, cs;
            sincospif((float)k * (1.0f / 1024.0f), &sn, &cs);    // w = (cs, -sn)
            const float xr = zer + cs * zor + sn * zoi;
            const float xi = zei + cs * zoi - sn * zor;
            mag = 0.5f * sqrtf(xr * xr + xi * xi);
        }
        (&g_bands[0][0][0])[((size_t)band * NROWS + row) * SKP + off] = mag;
    }
}

// ---------------------------------------------------------------------------
// Kernel 2: Y[k][r][d] = sum_s band[k][r][s] * Apad[k][d][s]
// 128x128 tiles, 256 threads, 8x8 per thread, f32x2 FMA, double-buffered smem
// ---------------------------------------------------------------------------
__global__ __launch_bounds__(256) void gemm_kernel() {
    __shared__ float Xs[2][16][128];
    __shared__ float As[2][16][128];

    const int k = blockIdx.z;
    const int d0 = blockIdx.x * 128;
    const int r0 = blockIdx.y * 128;
    const int t = threadIdx.x;
    const int tx = t & 15;
    const int ty = t >> 4;
    const float* band = &g_bands[k][0][0];
    const float* Ap = &g_Apad[k][0][0];

    const int lr = t & 127;          // row within tile for loading
    const int lh = (t >> 7) * 8;     // s-offset 0 or 8

    unsigned long long acc[8][4];
    #pragma unroll
    for (int i = 0; i < 8; i++)
        #pragma unroll
        for (int j = 0; j < 4; j++) acc[i][j] = 0ull;

    float4 bx0, bx1, ba0, ba1;

#define LDG_TILE(kt)                                                            \
    do {                                                                        \
        const float* xp = &band[(size_t)(r0 + lr) * SKP + (kt) + lh];           \
        const float* ap = &Ap[(size_t)(d0 + lr) * SKP + (kt) + lh];             \
        bx0 = *(const float4*)xp;  bx1 = *(const float4*)(xp + 4);              \
        ba0 = *(const float4*)ap;  ba1 = *(const float4*)(ap + 4);              \
    } while (0)

#define STS_TILE(buf)                                                           \
    do {                                                                        \
        Xs[buf][lh + 0][lr] = bx0.x;  Xs[buf][lh + 1][lr] = bx0.y;              \
        Xs[buf][lh + 2][lr] = bx0.z;  Xs[buf][lh + 3][lr] = bx0.w;              \
        Xs[buf][lh + 4][lr] = bx1.x;  Xs[buf][lh + 5][lr] = bx1.y;              \
        Xs[buf][lh + 6][lr] = bx1.z;  Xs[buf][lh + 7][lr] = bx1.w;              \
        As[buf][lh + 0][lr] = ba0.x;  As[buf][lh + 1][lr] = ba0.y;              \
        As[buf][lh + 2][lr] = ba0.z;  As[buf][lh + 3][lr] = ba0.w;              \
        As[buf][lh + 4][lr] = ba1.x;  As[buf][lh + 5][lr] = ba1.y;              \
        As[buf][lh + 6][lr] = ba1.z;  As[buf][lh + 7][lr] = ba1.w;              \
    } while (0)

    LDG_TILE(0);
    STS_TILE(0);
    __syncthreads();

    const int NT = SKP / 16;  // 22
    for (int kt = 0; kt < NT; kt++) {
        const int buf = kt & 1;
        if (kt + 1 < NT) LDG_TILE((kt + 1) * 16);

        #pragma unroll
        for (int kk = 0; kk < 16; kk++) {
            const float4 a0 = *(const float4*)&Xs[buf][kk][ty * 8];
            const float4 a1 = *(const float4*)&Xs[buf][kk][ty * 8 + 4];
            const float4 b0 = *(const float4*)&As[buf][kk][tx * 8];
            const float4 b1 = *(const float4*)&As[buf][kk][tx * 8 + 4];
            const unsigned long long bp0 = pk2(b0.x, b0.y);
            const unsigned long long bp1 = pk2(b0.z, b0.w);
            const unsigned long long bp2 = pk2(b1.x, b1.y);
            const unsigned long long bp3 = pk2(b1.z, b1.w);
            const float av[8] = {a0.x, a0.y, a0.z, a0.w, a1.x, a1.y, a1.z, a1.w};
            #pragma unroll
            for (int i = 0; i < 8; i++) {
                const unsigned long long ad = pk2(av[i], av[i]);
                fma2(acc[i][0], ad, bp0);
                fma2(acc[i][1], ad, bp1);
                fma2(acc[i][2], ad, bp2);
                fma2(acc[i][3], ad, bp3);
            }
        }
        if (kt + 1 < NT) STS_TILE(buf ^ 1);
        __syncthreads();
    }

    #pragma unroll
    for (int i = 0; i < 8; i++) {
        const int r = r0 + ty * 8 + i;
        float* yrow = &g_Y[k][r][0];
        #pragma unroll
        for (int j2 = 0; j2 < 4; j2++) {
            const int d = d0 + tx * 8 + j2 * 2;
            if (d < SKP) *(float2*)&yrow[d] = upk2(acc[i][j2]);
        }
    }
#undef LDG_TILE
#undef STS_TILE
}

// ---------------------------------------------------------------------------
// Kernel 3: per (batch b, band k): dist = relu(q_i + q_j - 2 * Yi.Yj)
// Transposed smem slab sYT[352][68]: inner loop = 2x LDS.128 + 8x FFMA2 per d.
// q extracted from Gram diagonal. grid (32, 3), 256 threads.
// ---------------------------------------------------------------------------
__global__ __launch_bounds__(256) void gram_dist_kernel() {
    extern __shared__ float sYT[];        // 352 * TSP floats (~95.7 KB)
    __shared__ float q[64];

    const int b = blockIdx.x;
    const int k = blockIdx.y;
    const int t = threadIdx.x;

    // load + transpose: g_Y[k][b*64 + r][*] -> sYT[d][r]
    // thread -> (r = t&7, c4 = t>>3): 16B-coalesced-per-row reads, 2-way STS
    {
        const int r_ = t & 7;
        const int c4_ = t >> 3;
        const float* src = &g_Y[k][b * 64][0];
        #pragma unroll
        for (int rb = 0; rb < 64; rb += 8) {
            const int r = rb + r_;
            #pragma unroll
            for (int cc = 0; cc < 3; cc++) {
                const int c4 = c4_ + 32 * cc;
                if (c4 < SKP / 4) {
                    const float4 v = *(const float4*)&src[(size_t)r * SKP + c4 * 4];
                    const int d = c4 * 4;
                    sYT[(d + 0) * TSP + r] = v.x;
                    sYT[(d + 1) * TSP + r] = v.y;
                    sYT[(d + 2) * TSP + r] = v.z;
                    sYT[(d + 3) * TSP + r] = v.w;
                }
            }
        }
    }
    __syncthreads();

    const int ty = t >> 4;
    const int tx = t & 15;
    const int ti = ty * 4;
    const int tj = tx * 4;

    unsigned long long acc[4][2];
    #pragma unroll
    for (int i = 0; i < 4; i++) { acc[i][0] = 0ull; acc[i][1] = 0ull; }

    #pragma unroll 4
    for (int d = 0; d < SKP; d++) {
        const float4 a = *(const float4*)&sYT[d * TSP + ti];          // broadcast
        const ulonglong2 bv = *(const ulonglong2*)&sYT[d * TSP + tj]; // conflict-free
        const unsigned long long a0 = pk2(a.x, a.x);
        const unsigned long long a1 = pk2(a.y, a.y);
        const unsigned long long a2 = pk2(a.z, a.z);
        const unsigned long long a3 = pk2(a.w, a.w);
        fma2(acc[0][0], a0, bv.x);  fma2(acc[0][1], a0, bv.y);
        fma2(acc[1][0], a1, bv.x);  fma2(acc[1][1], a1, bv.y);
        fma2(acc[2][0], a2, bv.x);  fma2(acc[2][1], a2, bv.y);
        fma2(acc[3][0], a3, bv.x);  fma2(acc[3][1], a3, bv.y);
    }

    // q_i = G_ii from the diagonal tiles (diagonal itself is masked downstream)
    if (ty == tx) {
        #pragma unroll
        for (int i = 0; i < 4; i++) {
            const float2 v = upk2(acc[i][i >> 1]);
            q[ti + i] = (i & 1) ? v.y : v.x;
        }
    }
    __syncthreads();

    #pragma unroll
    for (int i = 0; i < 4; i++) {
        const float qi = q[ti + i];
        #pragma unroll
        for (int jp = 0; jp < 2; jp++) {
            const float2 g = upk2(acc[i][jp]);
            const int jj = tj + jp * 2;
            float2 o;
            o.x = fmaxf(qi + q[jj + 0] - 2.0f * g.x, 0.0f);
            o.y = fmaxf(qi + q[jj + 1] - 2.0f * g.y, 0.0f);
            *(float2*)&g_dist[k][b][ti + i][jj] = o;
        }
    }
}

// ---------------------------------------------------------------------------
// Kernel 4: fuse bands, row-max of 1/dist, p, logits, gumbel argmax -> binary
// ---------------------------------------------------------------------------
__global__ __launch_bounds__(256) void mask_kernel(const float* __restrict__ fw,
                                                   const float* __restrict__ gum,
                                                   float* __restrict__ out) {
    const int t = threadIdx.x;
    const int g = t >> 6;               // row slice within block
    const int j = t & 63;
    const int bi = blockIdx.x * 4 + g;
    const int b = bi >> 6;
    const int i = bi & 63;

    const float f0 = fw[0], f1 = fw[1], f2 = fw[2];
    const float m = fmaxf(f0, fmaxf(f1, f2));
    const float e0 = expf(f0 - m), e1 = expf(f1 - m), e2 = expf(f2 - m);
    const float inv = 1.0f / (e0 + e1 + e2);
    const float w0 = e0 * inv, w1 = e1 * inv, w2 = e2 * inv;

    const float dsum = g_dist[0][b][i][j] * w0
                     + g_dist[1][b][i][j] * w1
                     + g_dist[2][b][i][j] * w2;

    const float e = 1.0f / (dsum + 1e-10f);
    const float emask = (j == i) ? 0.0f : e;

    __shared__ float red[8];
    float v = emask;
    #pragma unroll
    for (int o = 16; o; o >>= 1) v = fmaxf(v, __shfl_xor_sync(0xffffffffu, v, o));
    if ((t & 31) == 0) red[t >> 5] = v;
    __syncthreads();
    const float emax = fmaxf(red[2 * g], red[2 * g + 1]);

    float p = emask / emax;
    p = (j == i) ? 0.99f : p * 0.99f;

    const float l0 = logf(p / (1.0f - p));
    const float l1 = logf((1.0f - p) / p);

    const size_t gidx = ((size_t)(b * 4096 + i * 64 + j)) * 2;
    const float y0 = l0 + gum[gidx + 0];
    const float y1 = l1 + gum[gidx + 1];

    out[b * 4096 + i * 64 + j] = (y0 >= y1) ? 1.0f : 0.0f;
}

// ---------------------------------------------------------------------------
extern "C" void kernel_launch(void* const* d_in, const int* in_sizes, int n_in,
                              void* d_out, int out_size) {
    const float* X   = (const float*)d_in[0];
    const float* A0  = (const float*)d_in[1];
    const float* A1  = (const float*)d_in[2];
    const float* A2  = (const float*)d_in[3];
    const float* fw  = (const float*)d_in[4];
    const float* gum = (const float*)d_in[5];
    float* out = (float*)d_out;

    prep_kernel<<<dim3(DP, 3), 256>>>(A0, A1, A2);
    fft_kernel<<<NROWS, 256>>>(X);
    gemm_kernel<<<dim3(3, 16, 3), 256>>>();

    const int smem3 = SKP * TSP * sizeof(float);
    cudaFuncSetAttribute(gram_dist_kernel,
                         cudaFuncAttributeMaxDynamicSharedMemorySize, smem3);
    gram_dist_kernel<<<dim3(NB, 3), 256, smem3>>>();

    mask_kernel<<<512, 256>>>(fw, gum, out);
}

// round 5
// speedup vs baseline: 3.4127x; 1.0570x over previous
#include <cuda_runtime.h>
#include <math.h>

#define NB 32
#define NC 64
#define NL 2048
#define S0 341
#define S1 341
#define S2 343
#define SKP 352      // padded stride for bands / Y / Apad (K dim)
#define DP  384      // padded d dimension
#define TSP 68       // gram transposed-smem row stride (64 + 4)
#define NROWS 2048   // NB * NC

// Scratch (device globals; allocation-free per harness rules)
__device__ float g_bands[3][NROWS][SKP];
__device__ float g_Y[3][NROWS][SKP];
__device__ float g_Apad[3][DP][SKP];
__device__ float g_dist[3][NB][NC][NC];

// ---------------------------------------------------------------------------
// f32x2 helpers (Blackwell packed fp32: FFMA2)
// ---------------------------------------------------------------------------
__device__ __forceinline__ unsigned long long pk2(float lo, float hi) {
    unsigned long long r;
    asm("mov.b64 %0, {%1, %2};" : "=l"(r) : "f"(lo), "f"(hi));
    return r;
}
__device__ __forceinline__ void fma2(unsigned long long& d,
                                     unsigned long long a, unsigned long long b) {
    asm("fma.rn.f32x2 %0, %1, %2, %0;" : "+l"(d) : "l"(a), "l"(b));
}
__device__ __forceinline__ void add2(unsigned long long& d, unsigned long long a) {
    asm("add.rn.f32x2 %0, %0, %1;" : "+l"(d) : "l"(a));
}
__device__ __forceinline__ float2 upk2(unsigned long long v) {
    float lo, hi;
    asm("mov.b64 {%0, %1}, %2;" : "=f"(lo), "=f"(hi) : "l"(v));
    return make_float2(lo, hi);
}

// ---------------------------------------------------------------------------
// Kernel 0: pad A matrices into g_Apad (zero-filled to 384 x 352)
// ---------------------------------------------------------------------------
__global__ __launch_bounds__(256) void prep_kernel(const float* __restrict__ A0,
                                                   const float* __restrict__ A1,
                                                   const float* __restrict__ A2) {
    const int d = blockIdx.x;
    const int k = blockIdx.y;
    const int sk = (k == 2) ? S2 : S0;
    const float* A = (k == 0) ? A0 : ((k == 1) ? A1 : A2);
    float* dst = &g_Apad[k][d][0];
    for (int s = threadIdx.x; s < SKP; s += 256)
        dst[s] = (d < sk && s < sk) ? A[(size_t)d * sk + s] : 0.0f;
}

// ---------------------------------------------------------------------------
// Kernel 1: rfft magnitude via real-packed 1024-pt radix-4 FFT
// ---------------------------------------------------------------------------
__device__ __forceinline__ unsigned drev10(unsigned n) {
    unsigned r = __brev(n) >> 22;                       // 10-bit bit reversal
    return ((r & 0x155u) << 1) | ((r >> 1) & 0x155u);   // -> base-4 digit reversal
}

__global__ __launch_bounds__(256) void fft_kernel(const float* __restrict__ X) {
    __shared__ float sre[1024], sim[1024], wre[1025], wim[1025];
    const int row = blockIdx.x;
    const int t = threadIdx.x;
    const float2* x2 = (const float2*)(X + (size_t)row * NL);

    #pragma unroll
    for (int m = 0; m < 4; m++) {
        const int i = t + m * 256;
        float sn, cs;
        sincospif((float)i * (1.0f / 512.0f), &sn, &cs);  // e^{-2*pi*i*i/1024}
        wre[i] = cs;
        wim[i] = -sn;
        const float2 v = x2[i];       // z[i] = x[2i] + i*x[2i+1]
        const unsigned dr = drev10((unsigned)i);
        sre[dr] = v.x;
        sim[dr] = v.y;
    }
    if (t == 0) { wre[1024] = -1.0f; wim[1024] = 0.0f; }
    __syncthreads();

    // stage 1 (m=1): contiguous quads, twiddle = 1, float4 access
    {
        float4 xr = *(float4*)&sre[4 * t];
        float4 xi = *(float4*)&sim[4 * t];
        const float s02r = xr.x + xr.z, s02i = xi.x + xi.z;
        const float d02r = xr.x - xr.z, d02i = xi.x - xi.z;
        const float s13r = xr.y + xr.w, s13i = xi.y + xi.w;
        const float d13r = xr.y - xr.w, d13i = xi.y - xi.w;
        float4 yr, yi;
        yr.x = s02r + s13r;  yi.x = s02i + s13i;
        yr.y = d02r + d13i;  yi.y = d02i - d13r;
        yr.z = s02r - s13r;  yi.z = s02i - s13i;
        yr.w = d02r - d13i;  yi.w = d02i + d13r;
        *(float4*)&sre[4 * t] = yr;
        *(float4*)&sim[4 * t] = yi;
    }
    __syncthreads();

    // stages 2..5
    #pragma unroll
    for (int s = 2; s <= 5; s++) {
        const int mm = 1 << (2 * (s - 1));
        const int j = t & (mm - 1);
        const int base = ((t >> (2 * (s - 1))) << (2 * s)) + j;
        const int r1 = j << (10 - 2 * s);

        const float x0r = sre[base],          x0i = sim[base];
        const float x1r = sre[base + mm],     x1i = sim[base + mm];
        const float x2r = sre[base + 2 * mm], x2i = sim[base + 2 * mm];
        const float x3r = sre[base + 3 * mm], x3i = sim[base + 3 * mm];
        const float w1r = wre[r1],     w1i = wim[r1];
        const float w2r = wre[2 * r1], w2i = wim[2 * r1];
        const float w3r = wre[3 * r1], w3i = wim[3 * r1];

        const float u1r = x1r * w1r - x1i * w1i, u1i = x1r * w1i + x1i * w1r;
        const float u2r = x2r * w2r - x2i * w2i, u2i = x2r * w2i + x2i * w2r;
        const float u3r = x3r * w3r - x3i * w3i, u3i = x3r * w3i + x3i * w3r;

        const float s02r = x0r + u2r, s02i = x0i + u2i;
        const float d02r = x0r - u2r, d02i = x0i - u2i;
        const float s13r = u1r + u3r, s13i = u1i + u3i;
        const float d13r = u1r - u3r, d13i = u1i - u3i;

        sre[base]          = s02r + s13r;  sim[base]          = s02i + s13i;
        sre[base + mm]     = d02r + d13i;  sim[base + mm]     = d02i - d13r;
        sre[base + 2 * mm] = s02r - s13r;  sim[base + 2 * mm] = s02i - s13i;
        sre[base + 3 * mm] = d02r - d13i;  sim[base + 3 * mm] = d02i + d13r;
        __syncthreads();
    }

    // untangle real-packed spectrum + magnitude -> zero-padded band slabs
    // half-angle twiddle e^{-i*pi*k/1024}: even k -> LUT[k/2];
    // odd k -> LUT[k/2] * e^{-i*pi/1024} (hardcoded constant)
    const float CR = 0.999995293809576f;    // cos(pi/1024)
    const float CI = -0.003067956762966f;   // -sin(pi/1024)
    for (int pos = t; pos < 3 * SKP; pos += 256) {
        int band, off, k, sk;
        if (pos < SKP)            { band = 0; off = pos;           k = off;       sk = S0; }
        else if (pos < 2 * SKP)   { band = 1; off = pos - SKP;     k = S0 + off;  sk = S1; }
        else                      { band = 2; off = pos - 2 * SKP; k = 682 + off; sk = S2; }
        float mag = 0.0f;
        if (off < sk) {
            const int ka = k & 1023;
            const int kb = (1024 - k) & 1023;
            const float z1r = sre[ka], z1i = sim[ka];
            const float z2r = sre[kb], z2i = sim[kb];
            const float zer = z1r + z2r, zei = z1i - z2i;        // 2*Ze
            const float zor = z1i + z2i, zoi = z2r - z1r;        // 2*Zo
            const int m = k >> 1;
            float cs = wre[m], msn = wim[m];                     // e^{-i*pi*m/512}
            if (k & 1) {
                const float c2 = cs * CR - msn * CI;
                msn = cs * CI + msn * CR;
                cs = c2;
            }
            // w = (cs, msn) = e^{-i*pi*k/1024};  (matches cs = cospi, msn = -sinpi)
            const float xr = zer + cs * zor - msn * zoi;
            const float xi = zei + cs * zoi + msn * zor;
            mag = 0.5f * sqrtf(xr * xr + xi * xi);
        }
        (&g_bands[0][0][0])[((size_t)band * NROWS + row) * SKP + off] = mag;
    }
}

// ---------------------------------------------------------------------------
// Kernel 2: Y[k][r][d] = sum_s band[k][r][s] * Apad[k][d][s]
// 128(r) x 64(d) tiles -> 288 blocks (2 blocks/SM, 4 warps/SMSP)
// 256 threads, 8x4 per thread, f32x2 FMA, double-buffered smem
// grid (6, 16, 3)
// ---------------------------------------------------------------------------
__global__ __launch_bounds__(256) void gemm_kernel() {
    __shared__ float Xs[2][16][128];
    __shared__ float As[2][16][64];

    const int k = blockIdx.z;
    const int d0 = blockIdx.x * 64;
    const int r0 = blockIdx.y * 128;
    const int t = threadIdx.x;
    const int tx = t & 15;      // d group: 4 cols
    const int ty = t >> 4;      // r group: 8 rows
    const float* band = &g_bands[k][0][0];
    const float* Ap = &g_Apad[k][0][0];

    // X loader: 128 rows x 16 cols, 8 floats/thread
    const int xlr = t & 127;
    const int xlh = (t >> 7) * 8;
    // A loader: 64 rows x 16 cols, 4 floats/thread
    const int alr = t & 63;
    const int alh = (t >> 6) * 4;

    unsigned long long acc[8][2];
    #pragma unroll
    for (int i = 0; i < 8; i++) { acc[i][0] = 0ull; acc[i][1] = 0ull; }

    float4 bx0, bx1, ba0;

#define LDG_TILE(kt)                                                            \
    do {                                                                        \
        const float* xp = &band[(size_t)(r0 + xlr) * SKP + (kt) + xlh];         \
        const float* ap = &Ap[(size_t)(d0 + alr) * SKP + (kt) + alh];           \
        bx0 = *(const float4*)xp;  bx1 = *(const float4*)(xp + 4);              \
        ba0 = *(const float4*)ap;                                               \
    } while (0)

#define STS_TILE(buf)                                                           \
    do {                                                                        \
        Xs[buf][xlh + 0][xlr] = bx0.x;  Xs[buf][xlh + 1][xlr] = bx0.y;          \
        Xs[buf][xlh + 2][xlr] = bx0.z;  Xs[buf][xlh + 3][xlr] = bx0.w;          \
        Xs[buf][xlh + 4][xlr] = bx1.x;  Xs[buf][xlh + 5][xlr] = bx1.y;          \
        Xs[buf][xlh + 6][xlr] = bx1.z;  Xs[buf][xlh + 7][xlr] = bx1.w;          \
        As[buf][alh + 0][alr] = ba0.x;  As[buf][alh + 1][alr] = ba0.y;          \
        As[buf][alh + 2][alr] = ba0.z;  As[buf][alh + 3][alr] = ba0.w;          \
    } while (0)

    LDG_TILE(0);
    STS_TILE(0);
    __syncthreads();

    const int NT = SKP / 16;  // 22
    for (int kt = 0; kt < NT; kt++) {
        const int buf = kt & 1;
        if (kt + 1 < NT) LDG_TILE((kt + 1) * 16);

        #pragma unroll
        for (int kk = 0; kk < 16; kk++) {
            const float4 a0 = *(const float4*)&Xs[buf][kk][ty * 8];
            const float4 a1 = *(const float4*)&Xs[buf][kk][ty * 8 + 4];
            const float4 b0 = *(const float4*)&As[buf][kk][tx * 4];
            const unsigned long long bp0 = pk2(b0.x, b0.y);
            const unsigned long long bp1 = pk2(b0.z, b0.w);
            const float av[8] = {a0.x, a0.y, a0.z, a0.w, a1.x, a1.y, a1.z, a1.w};
            #pragma unroll
            for (int i = 0; i < 8; i++) {
                const unsigned long long ad = pk2(av[i], av[i]);
                fma2(acc[i][0], ad, bp0);
                fma2(acc[i][1], ad, bp1);
            }
        }
        if (kt + 1 < NT) STS_TILE(buf ^ 1);
        __syncthreads();
    }

    const int d = d0 + tx * 4;
    if (d < SKP) {
        #pragma unroll
        for (int i = 0; i < 8; i++) {
            const int r = r0 + ty * 8 + i;
            float* yrow = &g_Y[k][r][0];
            *(float2*)&yrow[d]     = upk2(acc[i][0]);
            *(float2*)&yrow[d + 2] = upk2(acc[i][1]);
        }
    }
#undef LDG_TILE
#undef STS_TILE
}

// ---------------------------------------------------------------------------
// Kernel 3: per (batch b, band k): dist = relu(q_i + q_j - 2 * Yi.Yj)
// 512 threads: two 256-thread halves each reduce 176 d-values (in-block
// K-split), combine via packed f32x2 adds through smem.
// grid (32, 3)
// ---------------------------------------------------------------------------
__global__ __launch_bounds__(512) void gram_dist_kernel() {
    extern __shared__ float sYT[];                 // 352 * TSP floats (~95.7 KB)
    __shared__ unsigned long long part[256][8];    // 16 KB partial accs
    __shared__ float q[64];

    const int b = blockIdx.x;
    const int k = blockIdx.y;
    const int t = threadIdx.x;

    // load + transpose: g_Y[k][b*64 + r][*] -> sYT[d][r], 512 threads
    {
        const int r_ = t & 7;
        const int c4_ = t >> 3;      // 0..63
        const float* src = &g_Y[k][b * 64][0];
        #pragma unroll
        for (int rb = 0; rb < 64; rb += 8) {
            const int r = rb + r_;
            #pragma unroll
            for (int cc = 0; cc < 2; cc++) {
                const int c4 = c4_ + 64 * cc;
                if (c4 < SKP / 4) {
                    const float4 v = *(const float4*)&src[(size_t)r * SKP + c4 * 4];
                    const int d = c4 * 4;
                    sYT[(d + 0) * TSP + r] = v.x;
                    sYT[(d + 1) * TSP + r] = v.y;
                    sYT[(d + 2) * TSP + r] = v.z;
                    sYT[(d + 3) * TSP + r] = v.w;
                }
            }
        }
    }
    __syncthreads();

    const int half = t >> 8;       // K-split group
    const int tt = t & 255;
    const int ty = tt >> 4;
    const int tx = tt & 15;
    const int ti = ty * 4;
    const int tj = tx * 4;

    unsigned long long acc[4][2];
    #pragma unroll
    for (int i = 0; i < 4; i++) { acc[i][0] = 0ull; acc[i][1] = 0ull; }

    const int dbeg = half * 176;
    #pragma unroll 4
    for (int dd = 0; dd < 176; dd++) {
        const int d = dbeg + dd;
        const float4 a = *(const float4*)&sYT[d * TSP + ti];          // broadcast
        const ulonglong2 bv = *(const ulonglong2*)&sYT[d * TSP + tj]; // conflict-free
        const unsigned long long a0 = pk2(a.x, a.x);
        const unsigned long long a1 = pk2(a.y, a.y);
        const unsigned long long a2 = pk2(a.z, a.z);
        const unsigned long long a3 = pk2(a.w, a.w);
        fma2(acc[0][0], a0, bv.x);  fma2(acc[0][1], a0, bv.y);
        fma2(acc[1][0], a1, bv.x);  fma2(acc[1][1], a1, bv.y);
        fma2(acc[2][0], a2, bv.x);  fma2(acc[2][1], a2, bv.y);
        fma2(acc[3][0], a3, bv.x);  fma2(acc[3][1], a3, bv.y);
    }

    if (half == 1) {
        #pragma unroll
        for (int i = 0; i < 4; i++) {
            part[tt][i * 2 + 0] = acc[i][0];
            part[tt][i * 2 + 1] = acc[i][1];
        }
    }
    __syncthreads();

    if (half == 0) {
        #pragma unroll
        for (int i = 0; i < 4; i++) {
            add2(acc[i][0], part[tt][i * 2 + 0]);
            add2(acc[i][1], part[tt][i * 2 + 1]);
        }
        // q_i = G_ii from the diagonal tiles (diagonal itself is masked downstream)
        if (ty == tx) {
            #pragma unroll
            for (int i = 0; i < 4; i++) {
                const float2 v = upk2(acc[i][i >> 1]);
                q[ti + i] = (i & 1) ? v.y : v.x;
            }
        }
    }
    __syncthreads();

    if (half == 0) {
        #pragma unroll
        for (int i = 0; i < 4; i++) {
            const float qi = q[ti + i];
            #pragma unroll
            for (int jp = 0; jp < 2; jp++) {
                const float2 g = upk2(acc[i][jp]);
                const int jj = tj + jp * 2;
                float2 o;
                o.x = fmaxf(qi + q[jj + 0] - 2.0f * g.x, 0.0f);
                o.y = fmaxf(qi + q[jj + 1] - 2.0f * g.y, 0.0f);
                *(float2*)&g_dist[k][b][ti + i][jj] = o;
            }
        }
    }
}

// ---------------------------------------------------------------------------
// Kernel 4: fuse bands, row-max of 1/dist, p, logits, gumbel argmax -> binary
// ---------------------------------------------------------------------------
__global__ __launch_bounds__(256) void mask_kernel(const float* __restrict__ fw,
                                                   const float* __restrict__ gum,
                                                   float* __restrict__ out) {
    const int t = threadIdx.x;
    const int g = t >> 6;               // row slice within block
    const int j = t & 63;
    const int bi = blockIdx.x * 4 + g;
    const int b = bi >> 6;
    const int i = bi & 63;

    const float f0 = fw[0], f1 = fw[1], f2 = fw[2];
    const float m = fmaxf(f0, fmaxf(f1, f2));
    const float e0 = expf(f0 - m), e1 = expf(f1 - m), e2 = expf(f2 - m);
    const float inv = 1.0f / (e0 + e1 + e2);
    const float w0 = e0 * inv, w1 = e1 * inv, w2 = e2 * inv;

    const float dsum = g_dist[0][b][i][j] * w0
                     + g_dist[1][b][i][j] * w1
                     + g_dist[2][b][i][j] * w2;

    const float e = 1.0f / (dsum + 1e-10f);
    const float emask = (j == i) ? 0.0f : e;

    __shared__ float red[8];
    float v = emask;
    #pragma unroll
    for (int o = 16; o; o >>= 1) v = fmaxf(v, __shfl_xor_sync(0xffffffffu, v, o));
    if ((t & 31) == 0) red[t >> 5] = v;
    __syncthreads();
    const float emax = fmaxf(red[2 * g], red[2 * g + 1]);

    float p = emask / emax;
    p = (j == i) ? 0.99f : p * 0.99f;

    const float l0 = logf(p / (1.0f - p));
    const float l1 = logf((1.0f - p) / p);

    const size_t gidx = ((size_t)(b * 4096 + i * 64 + j)) * 2;
    const float y0 = l0 + gum[gidx + 0];
    const float y1 = l1 + gum[gidx + 1];

    out[b * 4096 + i * 64 + j] = (y0 >= y1) ? 1.0f : 0.0f;
}

// ---------------------------------------------------------------------------
extern "C" void kernel_launch(void* const* d_in, const int* in_sizes, int n_in,
                              void* d_out, int out_size) {
    const float* X   = (const float*)d_in[0];
    const float* A0  = (const float*)d_in[1];
    const float* A1  = (const float*)d_in[2];
    const float* A2  = (const float*)d_in[3];
    const float* fw  = (const float*)d_in[4];
    const float* gum = (const float*)d_in[5];
    float* out = (float*)d_out;

    prep_kernel<<<dim3(DP, 3), 256>>>(A0, A1, A2);
    fft_kernel<<<NROWS, 256>>>(X);
    gemm_kernel<<<dim3(6, 16, 3), 256>>>();

    const int smem3 = SKP * TSP * sizeof(float);
    cudaFuncSetAttribute(gram_dist_kernel,
                         cudaFuncAttributeMaxDynamicSharedMemorySize, smem3);
    gram_dist_kernel<<<dim3(NB, 3), 512, smem3>>>();

    mask_kernel<<<512, 256>>>(fw, gum, out);
}